// round 8
// baseline (speedup 1.0000x reference)
#include <cuda_runtime.h>
#include <cuda_bf16.h>

#define EPS_F 1e-7f

// Fused single-kernel Lorentz boost, 8 four-vectors per thread.
// Each thread computes its channel's coefficients once (2x rsqrt, hidden under
// DRAM latency) then streams 8 float4s of the SAME channel at stride 2^20
// (multiple of 1024 -> same channel; warp-adjacent threads stay coalesced).
// 8 front-batched LDG.128 per thread (MLP_p1=8) keep the LSU/DRAM queues full
// at the reduced occupancy (~4 blocks/SM) that the register footprint forces.
// .cs streaming hints keep the zero-reuse 256MB T/out traffic from thrashing L2.
__global__ __launch_bounds__(256) void lorentz_fused8_kernel(
    const float4* __restrict__ T4,
    const float*  __restrict__ Bo,
    float4* __restrict__ out4)
{
    const unsigned tid = blockIdx.x * 256u + threadIdx.x;   // 0 .. 2^20-1
    const int c = tid & 1023;

    // ---- per-channel coefficients ----
    const float b0 = __ldg(&Bo[3 * c + 0]);
    const float b1 = __ldg(&Bo[3 * c + 1]);
    const float b2 = __ldg(&Bo[3 * c + 2]);
    const float m2 = fmaf(b0, b0, fmaf(b1, b1, b2 * b2));

    float n0, n1, n2, g;
    const float mag  = sqrtf(m2);
    const float magc = fminf(fmaxf(mag, EPS_F), 1.0f - EPS_F);
    if (magc == mag) {
        const float inv = rsqrtf(m2);
        n0 = b0 * inv; n1 = b1 * inv; n2 = b2 * inv;
        g  = rsqrtf(1.0f - m2);
    } else {
        // exact reference semantics when mag is clipped (rare/never on this data)
        n0 = b0 / magc; n1 = b1 / magc; n2 = b2 / magc;
        g  = rsqrtf(1.0f - magc * magc);
    }
    const float gb  = g * magc;   // g * mag
    const float gm1 = g - 1.0f;

    // ---- stream 8 elements ----
    const unsigned STRIDE = 1u << 20;  // 1,048,576 float4s (multiple of 1024)

    float4 x[8];
#pragma unroll
    for (int i = 0; i < 8; i++)
        x[i] = __ldcs(&T4[tid + (unsigned)i * STRIDE]);

#pragma unroll
    for (int i = 0; i < 8; i++) {
        float dot = fmaf(n0, x[i].y, fmaf(n1, x[i].z, n2 * x[i].w));
        float k   = fmaf(gm1, dot, -(gb * x[i].x));   // (g-1)(n.v) - g*mag*t
        float4 o;
        o.x = fmaf(g, x[i].x, -(gb * dot));           // g*t - g*mag*(n.v)
        o.y = fmaf(n0, k, x[i].y);
        o.z = fmaf(n1, k, x[i].z);
        o.w = fmaf(n2, k, x[i].w);
        x[i] = o;   // reuse registers
    }

#pragma unroll
    for (int i = 0; i < 8; i++)
        __stcs(&out4[tid + (unsigned)i * STRIDE], x[i]);
}

extern "C" void kernel_launch(void* const* d_in, const int* in_sizes, int n_in,
                              void* d_out, int out_size) {
    const float* T  = (const float*)d_in[0];   // 8192*1024*4 fp32
    const float* Bo = (const float*)d_in[1];   // 1024*3 fp32
    float* out = (float*)d_out;

    // 8192*1024 = 2^23 four-vectors; 8 per thread -> 2^20 threads -> 4096 blocks
    lorentz_fused8_kernel<<<4096, 256>>>((const float4*)T, Bo, (float4*)out);
}